// round 5
// baseline (speedup 1.0000x reference)
#include <cuda_runtime.h>
#include <math.h>

#define TS   512
#define NB   32
#define DIN  512
#define HID  1024
#define G2   2048
#define NPAIR 16            // 32 batches as 16 pairs

// ---------------- global scratch ----------------
// pair-interleaved state: [pair][col][2]  (col < HID for h/rh/u)
__device__ float g_XG[(size_t)TS * NB * G2];
__device__ float g_XC[(size_t)TS * NB * HID];
__device__ float g_h2 [NPAIR * HID * 2];
__device__ float g_rh2[NPAIR * HID * 2];
__device__ float g_u2 [NPAIR * HID * 2];
__device__ unsigned int g_barg[8 * 64];

__global__ void gru_init_kernel() {
    int idx = blockIdx.x * blockDim.x + threadIdx.x;
    if (idx < NPAIR * HID * 2) g_h2[idx] = 0.0f;
    if (idx < 8 * 64) g_barg[idx] = 0u;
}

// ---------------- f32x2 helpers ----------------
typedef unsigned long long ull;
__device__ __forceinline__ ull pack2(float x) {
    ull r; asm("mov.b64 %0, {%1, %1};" : "=l"(r) : "f"(x)); return r;
}
__device__ __forceinline__ void ffma2(ull& acc, ull a, ull b) {
    asm("fma.rn.f32x2 %0, %1, %2, %0;" : "+l"(acc) : "l"(a), "l"(b));
}

// ---------------- precompute GEMM (unchanged) ----------------
#define BM 128
#define BN 64
#define BK 16
#define APAD 132

__global__ void __launch_bounds__(256) sgemm_bias_kernel(
    const float* __restrict__ A, const float* __restrict__ W,
    const float* __restrict__ bias, float* __restrict__ C,
    int M, int N, int K, int ldw)
{
    __shared__ float As[BK * APAD];
    __shared__ float Ws[BK * BN];

    const int tid = threadIdx.x;
    const int tx = tid & 15;
    const int ty = tid >> 4;
    const int m0 = blockIdx.y * BM;
    const int n0 = blockIdx.x * BN;

    float acc[8][4];
#pragma unroll
    for (int i = 0; i < 8; ++i)
#pragma unroll
        for (int j = 0; j < 4; ++j) acc[i][j] = 0.0f;

    for (int k0 = 0; k0 < K; k0 += BK) {
        {
            const int kq = tid & 3;
            const int mr = tid >> 2;
#pragma unroll
            for (int it = 0; it < 2; ++it) {
                int m = mr + it * 64;
                float4 v = *(const float4*)&A[(size_t)(m0 + m) * K + k0 + kq * 4];
                As[(kq * 4 + 0) * APAD + m] = v.x;
                As[(kq * 4 + 1) * APAD + m] = v.y;
                As[(kq * 4 + 2) * APAD + m] = v.z;
                As[(kq * 4 + 3) * APAD + m] = v.w;
            }
        }
        {
            const int nq = tid & 15;
            const int kr = tid >> 4;
            float4 v = *(const float4*)&W[(size_t)(k0 + kr) * ldw + n0 + nq * 4];
            *(float4*)&Ws[kr * BN + nq * 4] = v;
        }
        __syncthreads();
#pragma unroll
        for (int kk = 0; kk < BK; ++kk) {
            float4 w4 = *(const float4*)&Ws[kk * BN + tx * 4];
            float4 a0 = *(const float4*)&As[kk * APAD + ty * 8];
            float4 a1 = *(const float4*)&As[kk * APAD + ty * 8 + 4];
            float a[8];
            a[0] = a0.x; a[1] = a0.y; a[2] = a0.z; a[3] = a0.w;
            a[4] = a1.x; a[5] = a1.y; a[6] = a1.z; a[7] = a1.w;
#pragma unroll
            for (int i = 0; i < 8; ++i) {
                acc[i][0] += a[i] * w4.x;
                acc[i][1] += a[i] * w4.y;
                acc[i][2] += a[i] * w4.z;
                acc[i][3] += a[i] * w4.w;
            }
        }
        __syncthreads();
    }

    float4 bv = *(const float4*)&bias[n0 + tx * 4];
#pragma unroll
    for (int i = 0; i < 8; ++i) {
        float4 o;
        o.x = acc[i][0] + bv.x;
        o.y = acc[i][1] + bv.y;
        o.z = acc[i][2] + bv.z;
        o.w = acc[i][3] + bv.w;
        *(float4*)&C[(size_t)(m0 + ty * 8 + i) * N + n0 + tx * 4] = o;
    }
}

// ---------------- persistent recurrence ----------------
#define RBLOCKS  128
#define RTHREADS 512
#define CK       256                 // k per chunk
#define HROW     36                  // floats per k-row in Hc (32 data + 4 pad)
#define HC_BUF   (CK * HROW)         // 9216 floats per buffer

// dynamic smem layout (floats)
#define OFF_WG   0                   // [1024][16]   16384
#define OFF_WC   16384               // [1024][8]     8192
#define OFF_HC   24576               // 2 x 9216     18432
#define OFF_RED  43008               // 16 x 544      8704
#define SMEM_FLOATS 51712            // 206848 bytes

#define SWZ(k)  (((k) & 7) ^ (((k) >> 3) & 7))

__device__ __forceinline__ void grid_barrier_h(unsigned* target) {
    __syncthreads();
    if (threadIdx.x == 0) {
        __threadfence();
        atomicAdd(&g_barg[(blockIdx.x >> 4) * 64], 1u);
    }
    *target += 16;
    if (threadIdx.x < 8) {
        volatile unsigned* c = &g_barg[threadIdx.x * 64];
        while (*c < *target) { }
    }
    __threadfence();
    __syncthreads();
}

// stage chunk c of pair-interleaved state (rows of 2*HID floats) into regs / smem
__device__ __forceinline__ void stage_ldg(const float* __restrict__ src, int c, float4* r) {
    const int tid = threadIdx.x;
#pragma unroll
    for (int it = 0; it < 4; ++it) {
        int u = tid + it * 512;
        int bp = u >> 7, q = u & 127;
        r[it] = __ldcg((const float4*)&src[bp * (HID * 2) + c * (CK * 2) + q * 4]);
    }
}
__device__ __forceinline__ void stage_sts(float* __restrict__ Hb, const float4* r) {
    const int tid = threadIdx.x;
#pragma unroll
    for (int it = 0; it < 4; ++it) {
        int u = tid + it * 512;
        int bp = u >> 7, q = u & 127;
        int k0 = q * 2, k1 = q * 2 + 1;
        int g = bp >> 1, sub = (bp & 1) * 2;
        float2 a; a.x = r[it].x; a.y = r[it].y;
        float2 b; b.x = r[it].z; b.y = r[it].w;
        *(float2*)&Hb[k0 * HROW + ((g ^ SWZ(k0)) << 2) + sub] = a;
        *(float2*)&Hb[k1 * HROW + ((g ^ SWZ(k1)) << 2) + sub] = b;
    }
}

__global__ void __launch_bounds__(RTHREADS, 1) gru_recurrent_kernel(
    const float* __restrict__ gk,
    const float* __restrict__ ck,
    float* __restrict__ out)
{
    extern __shared__ float smem[];
    float* WgS = smem + OFF_WG;
    float* WcS = smem + OFF_WC;
    float* Hc  = smem + OFF_HC;
    float* Red = smem + OFF_RED;

    const int tid  = threadIdx.x;
    const int lane = tid & 31;
    const int s    = tid >> 5;        // k-slice (warp), 0..15

    const int p = blockIdx.x;
    const float* __restrict__ Ug = gk + (size_t)DIN * G2;
    const float* __restrict__ Uc = ck + (size_t)DIN * HID;
    const int jbaseA = p * 16;
    const int jbaseB = p * 8;

    // ---- preload weight slices into SMEM (once) ----
#pragma unroll
    for (int it = 0; it < 8; ++it) {
        int u = tid + it * 512;               // 0..4095
        int k = u >> 2, jq = u & 3;
        float4 v = *(const float4*)&Ug[(size_t)k * G2 + jbaseA + jq * 4];
        *(float4*)&WgS[k * 16 + jq * 4] = v;
    }
#pragma unroll
    for (int it = 0; it < 4; ++it) {
        int u = tid + it * 512;               // 0..2047
        int k = u >> 1, jq = u & 1;
        float4 v = *(const float4*)&Uc[(size_t)k * HID + jbaseB + jq * 4];
        *(float4*)&WcS[k * 8 + jq * 4] = v;
    }
    __syncthreads();

    // phase A tile: lanes = 8 bpg x 4 jg(4 j each); thread: 2 pairs x 4 j
    const int bpgA = lane & 7;
    const int jgA  = lane >> 3;       // 0..3
    // phase B tile: lanes = 8 bpg x 4 jg(2 j each); thread: 2 pairs x 2 j
    const int bpgB = lane & 7;
    const int jgB  = lane >> 3;       // 0..3

    unsigned bar_target = 0;

    for (int t = 0; t < TS; ++t) {
        // =================== Phase A: gates ===================
        // prefetch epilogue operands (threads 0..255 -> out (bp, j))
        float xg0 = 0.f, xg1 = 0.f; float2 hE = make_float2(0.f, 0.f);
        if (tid < 256) {
            int bp = tid >> 4, j = tid & 15;
            int jcol = jbaseA + j;
            xg0 = __ldcg(&g_XG[((size_t)((bp * 2 + 0) * TS + t)) * G2 + jcol]);
            xg1 = __ldcg(&g_XG[((size_t)((bp * 2 + 1) * TS + t)) * G2 + jcol]);
            if (p < 64) hE = __ldcg((const float2*)&g_h2[bp * (HID * 2) + jcol * 2]);
        }
        {
            float4 r[4];
            stage_ldg(g_h2, 0, r);
            stage_sts(Hc, r);
        }
        __syncthreads();

        ull acc[8];
#pragma unroll
        for (int i = 0; i < 8; ++i) acc[i] = 0ull;

        for (int c = 0; c < 4; ++c) {
            float4 r[4];
            if (c < 3) stage_ldg(g_h2, c + 1, r);
            const float* Hb = Hc + (c & 1) * HC_BUF;
            const int kl0 = s * 16;
#pragma unroll
            for (int kk = 0; kk < 16; ++kk) {
                const int kl = kl0 + kk;
                const int kg = c * CK + kl;
                longlong2 hq = *(const longlong2*)&Hb[kl * HROW + ((bpgA ^ SWZ(kl)) << 2)];
                ull h0 = (ull)hq.x, h1 = (ull)hq.y;
                float4 w4 = *(const float4*)&WgS[kg * 16 + jgA * 4];
                ull wx = pack2(w4.x), wy = pack2(w4.y), wz = pack2(w4.z), ww = pack2(w4.w);
                ffma2(acc[0], h0, wx); ffma2(acc[1], h0, wy);
                ffma2(acc[2], h0, wz); ffma2(acc[3], h0, ww);
                ffma2(acc[4], h1, wx); ffma2(acc[5], h1, wy);
                ffma2(acc[6], h1, wz); ffma2(acc[7], h1, ww);
            }
            if (c < 3) stage_sts(Hc + ((c + 1) & 1) * HC_BUF, r);
            __syncthreads();
        }
        // write partials: out = bp*16 + j, bp = bpgA*2+i, j = jgA*4+jj
#pragma unroll
        for (int i = 0; i < 2; ++i)
#pragma unroll
            for (int jj = 0; jj < 4; ++jj)
                *(ull*)&Red[s * 544 + ((bpgA * 2 + i) * 16 + jgA * 4 + jj) * 2] = acc[i * 4 + jj];
        __syncthreads();
        if (tid < 256) {
            float sx = 0.f, sy = 0.f;
#pragma unroll
            for (int ss = 0; ss < 16; ++ss) {
                float2 v = *(const float2*)&Red[ss * 544 + tid * 2];
                sx += v.x; sy += v.y;
            }
            int bp = tid >> 4, j = tid & 15;
            int jcol = jbaseA + j;
            float s0 = 1.0f / (1.0f + expf(-(sx + xg0)));
            float s1 = 1.0f / (1.0f + expf(-(sy + xg1)));
            if (p < 64) {
                float2 o; o.x = s0 * hE.x; o.y = s1 * hE.y;
                __stcg((float2*)&g_rh2[bp * (HID * 2) + jcol * 2], o);
            } else {
                float2 o; o.x = s0; o.y = s1;
                __stcg((float2*)&g_u2[bp * (HID * 2) + (jcol - HID) * 2], o);
            }
        }
        grid_barrier_h(&bar_target);

        // =================== Phase B: candidate + update ===================
        float xc0 = 0.f, xc1 = 0.f;
        float2 uE = make_float2(0.f, 0.f), hB = make_float2(0.f, 0.f);
        if (tid < 128) {
            int bp = tid >> 3, j = tid & 7;
            int jcol = jbaseB + j;
            xc0 = __ldcg(&g_XC[((size_t)((bp * 2 + 0) * TS + t)) * HID + jcol]);
            xc1 = __ldcg(&g_XC[((size_t)((bp * 2 + 1) * TS + t)) * HID + jcol]);
            uE = __ldcg((const float2*)&g_u2[bp * (HID * 2) + jcol * 2]);
            hB = __ldcg((const float2*)&g_h2[bp * (HID * 2) + jcol * 2]);
        }
        {
            float4 r[4];
            stage_ldg(g_rh2, 0, r);
            stage_sts(Hc, r);
        }
        __syncthreads();

        ull accB[4];
#pragma unroll
        for (int i = 0; i < 4; ++i) accB[i] = 0ull;

        for (int c = 0; c < 4; ++c) {
            float4 r[4];
            if (c < 3) stage_ldg(g_rh2, c + 1, r);
            const float* Hb = Hc + (c & 1) * HC_BUF;
            const int kl0 = s * 16;
#pragma unroll
            for (int kk = 0; kk < 16; ++kk) {
                const int kl = kl0 + kk;
                const int kg = c * CK + kl;
                longlong2 hq = *(const longlong2*)&Hb[kl * HROW + ((bpgB ^ SWZ(kl)) << 2)];
                ull h0 = (ull)hq.x, h1 = (ull)hq.y;
                float2 w2 = *(const float2*)&WcS[kg * 8 + jgB * 2];
                ull wx = pack2(w2.x), wy = pack2(w2.y);
                ffma2(accB[0], h0, wx); ffma2(accB[1], h0, wy);
                ffma2(accB[2], h1, wx); ffma2(accB[3], h1, wy);
            }
            if (c < 3) stage_sts(Hc + ((c + 1) & 1) * HC_BUF, r);
            __syncthreads();
        }
        // out = bp*8 + j, bp = bpgB*2+i, j = jgB*2+jj
#pragma unroll
        for (int i = 0; i < 2; ++i)
#pragma unroll
            for (int jj = 0; jj < 2; ++jj)
                *(ull*)&Red[s * 288 + ((bpgB * 2 + i) * 8 + jgB * 2 + jj) * 2] = accB[i * 2 + jj];
        __syncthreads();
        if (tid < 128) {
            float sx = 0.f, sy = 0.f;
#pragma unroll
            for (int ss = 0; ss < 16; ++ss) {
                float2 v = *(const float2*)&Red[ss * 288 + tid * 2];
                sx += v.x; sy += v.y;
            }
            int bp = tid >> 3, j = tid & 7;
            int jcol = jbaseB + j;
            float c0 = tanhf(sx + xc0);
            float c1 = tanhf(sy + xc1);
            float hn0 = uE.x * hB.x + (1.0f - uE.x) * c0;
            float hn1 = uE.y * hB.y + (1.0f - uE.y) * c1;
            float2 o; o.x = hn0; o.y = hn1;
            __stcg((float2*)&g_h2[bp * (HID * 2) + jcol * 2], o);
            out[((size_t)(bp * 2 + 0) * TS + t) * HID + jcol] = hn0;
            out[((size_t)(bp * 2 + 1) * TS + t) * HID + jcol] = hn1;
        }
        grid_barrier_h(&bar_target);
    }
}

// ---------------- launch ----------------
extern "C" void kernel_launch(void* const* d_in, const int* in_sizes, int n_in,
                              void* d_out, int out_size) {
    const float* X  = (const float*)d_in[0];
    const float* gk = (const float*)d_in[1];
    const float* gb = (const float*)d_in[2];
    const float* ck = (const float*)d_in[3];
    const float* cb = (const float*)d_in[4];
    float* out = (float*)d_out;
    (void)in_sizes; (void)n_in; (void)out_size;

    void* pa = nullptr; void* pb = nullptr;
    cudaGetSymbolAddress(&pa, g_XG);
    cudaGetSymbolAddress(&pb, g_XC);
    float* xg_ptr = (float*)pa;
    float* xc_ptr = (float*)pb;

    cudaFuncSetAttribute(gru_recurrent_kernel,
                         cudaFuncAttributeMaxDynamicSharedMemorySize,
                         SMEM_FLOATS * (int)sizeof(float));

    gru_init_kernel<<<RBLOCKS, 256>>>();
    {
        dim3 grid(G2 / BN, (NB * TS) / BM);
        sgemm_bias_kernel<<<grid, 256>>>(X, gk, gb, xg_ptr, NB * TS, G2, DIN, G2);
    }
    {
        dim3 grid(HID / BN, (NB * TS) / BM);
        sgemm_bias_kernel<<<grid, 256>>>(X, ck, cb, xc_ptr, NB * TS, HID, DIN, HID);
    }
    gru_recurrent_kernel<<<RBLOCKS, RTHREADS, SMEM_FLOATS * sizeof(float)>>>(gk, ck, out);
}

// round 7
// speedup vs baseline: 1.3154x; 1.3154x over previous
#include <cuda_runtime.h>
#include <math.h>

#define TS   512
#define NB   32
#define DIN  512
#define HID  1024
#define G2   2048

// ---------------- global scratch ----------------
__device__ float g_XG[(size_t)TS * NB * G2];
__device__ float g_XC[(size_t)TS * NB * HID];
__device__ float g_h [NB * HID];
__device__ float g_rh[NB * HID];
__device__ float g_u [NB * HID];
__device__ unsigned int g_barg[8 * 64];

__global__ void gru_init_kernel() {
    int idx = blockIdx.x * blockDim.x + threadIdx.x;
    if (idx < NB * HID) g_h[idx] = 0.0f;
    if (idx < 8 * 64) g_barg[idx] = 0u;
}

// ---------------- precompute GEMM (unchanged, ~70% fp32 peak) ----------------
#define BM 128
#define BN 64
#define BK 16
#define APAD 132

__global__ void __launch_bounds__(256) sgemm_bias_kernel(
    const float* __restrict__ A, const float* __restrict__ W,
    const float* __restrict__ bias, float* __restrict__ C,
    int M, int N, int K, int ldw)
{
    __shared__ float As[BK * APAD];
    __shared__ float Ws[BK * BN];

    const int tid = threadIdx.x;
    const int tx = tid & 15;
    const int ty = tid >> 4;
    const int m0 = blockIdx.y * BM;
    const int n0 = blockIdx.x * BN;

    float acc[8][4];
#pragma unroll
    for (int i = 0; i < 8; ++i)
#pragma unroll
        for (int j = 0; j < 4; ++j) acc[i][j] = 0.0f;

    for (int k0 = 0; k0 < K; k0 += BK) {
        {
            const int kq = tid & 3;
            const int mr = tid >> 2;
#pragma unroll
            for (int it = 0; it < 2; ++it) {
                int m = mr + it * 64;
                float4 v = *(const float4*)&A[(size_t)(m0 + m) * K + k0 + kq * 4];
                As[(kq * 4 + 0) * APAD + m] = v.x;
                As[(kq * 4 + 1) * APAD + m] = v.y;
                As[(kq * 4 + 2) * APAD + m] = v.z;
                As[(kq * 4 + 3) * APAD + m] = v.w;
            }
        }
        {
            const int nq = tid & 15;
            const int kr = tid >> 4;
            float4 v = *(const float4*)&W[(size_t)(k0 + kr) * ldw + n0 + nq * 4];
            *(float4*)&Ws[kr * BN + nq * 4] = v;
        }
        __syncthreads();
#pragma unroll
        for (int kk = 0; kk < BK; ++kk) {
            float4 w4 = *(const float4*)&Ws[kk * BN + tx * 4];
            float4 a0 = *(const float4*)&As[kk * APAD + ty * 8];
            float4 a1 = *(const float4*)&As[kk * APAD + ty * 8 + 4];
            float a[8];
            a[0] = a0.x; a[1] = a0.y; a[2] = a0.z; a[3] = a0.w;
            a[4] = a1.x; a[5] = a1.y; a[6] = a1.z; a[7] = a1.w;
#pragma unroll
            for (int i = 0; i < 8; ++i) {
                acc[i][0] += a[i] * w4.x;
                acc[i][1] += a[i] * w4.y;
                acc[i][2] += a[i] * w4.z;
                acc[i][3] += a[i] * w4.w;
            }
        }
        __syncthreads();
    }

    float4 bv = *(const float4*)&bias[n0 + tx * 4];
#pragma unroll
    for (int i = 0; i < 8; ++i) {
        float4 o;
        o.x = acc[i][0] + bv.x;
        o.y = acc[i][1] + bv.y;
        o.z = acc[i][2] + bv.z;
        o.w = acc[i][3] + bv.w;
        *(float4*)&C[(size_t)(m0 + ty * 8 + i) * N + n0 + tx * 4] = o;
    }
}

// ---------------- persistent recurrence (mma tf32, 3-pass) ----------------
#define RBLOCKS  128
#define RTHREADS 256
#define CK       256               // k per staged chunk
#define HSTRIDE  260               // h tile row stride (floats): (4b+k)%32 distinct
#define HCBUF    (32 * HSTRIDE)    // 8320 floats per buffer

// dynamic smem layout (float offsets)
#define OFF_WG0  0                 // Wg cols j0..7   [1024][8]
#define OFF_WG1  8192              // Wg cols j8..15  [1024][8]
#define OFF_WC   16384             // Wc cols j0..7   [1024][8]
#define OFF_HC   24576             // 2 x 8320
#define OFF_RED  41216             // 8 warps x 512
#define SMEM_FLOATS 45312          // 181248 bytes

// ---- PTX helpers ----
__device__ __forceinline__ unsigned tf32_of(float f) {
    unsigned r; asm("cvt.rna.tf32.f32 %0, %1;" : "=r"(r) : "f"(f)); return r;
}
__device__ __forceinline__ void mma_tf32(float* c, const unsigned* a, const unsigned* b) {
    asm("mma.sync.aligned.m16n8k8.row.col.f32.tf32.tf32.f32 "
        "{%0,%1,%2,%3}, {%4,%5,%6,%7}, {%8,%9}, {%0,%1,%2,%3};"
        : "+f"(c[0]), "+f"(c[1]), "+f"(c[2]), "+f"(c[3])
        : "r"(a[0]), "r"(a[1]), "r"(a[2]), "r"(a[3]), "r"(b[0]), "r"(b[1]));
}
__device__ __forceinline__ void cp16(unsigned saddr, const void* g) {
    asm volatile("cp.async.cg.shared.global [%0], [%1], 16;" :: "r"(saddr), "l"(g));
}
#define CP_COMMIT() asm volatile("cp.async.commit_group;")
#define CP_WAIT(n)  asm volatile("cp.async.wait_group %0;" :: "n"(n))

__device__ __forceinline__ void grid_barrier_h(unsigned* target) {
    __syncthreads();
    if (threadIdx.x == 0) {
        __threadfence();
        atomicAdd(&g_barg[(blockIdx.x >> 4) * 64], 1u);
    }
    *target += 16;
    if (threadIdx.x < 8) {
        volatile unsigned* c = &g_barg[threadIdx.x * 64];
        while (*c < *target) { }
    }
    __threadfence();
    __syncthreads();
}

// stage chunk c (32 batches x CK k) of src [b][1024] into smem buf [b][k] via cp.async.cg
__device__ __forceinline__ void issue_chunk(unsigned sbase, const float* __restrict__ src,
                                            int c, int buf) {
    const int tid = threadIdx.x;
#pragma unroll
    for (int it = 0; it < 8; ++it) {
        int u = tid + it * 256;          // 0..2047
        int b = u >> 6, kq = u & 63;
        const float* gp = src + b * HID + c * CK + kq * 4;
        unsigned sa = sbase + (unsigned)((OFF_HC + buf * HCBUF + b * HSTRIDE + kq * 4) * 4);
        cp16(sa, gp);
    }
}

// load A fragments (2 m-tiles, hi+lo) for one k8 from staged h tile
__device__ __forceinline__ void load_afrag(const float* __restrict__ Hb, int kloc,
                                           int g, int tg, unsigned ahi[2][4], unsigned alo[2][4]) {
#pragma unroll
    for (int m = 0; m < 2; ++m)
#pragma unroll
        for (int r = 0; r < 4; ++r) {
            int row = m * 16 + g + (r & 1) * 8;
            int col = kloc + tg + (r >> 1) * 4;
            float f = Hb[row * HSTRIDE + col];
            unsigned hi = tf32_of(f);
            ahi[m][r] = hi;
            alo[m][r] = tf32_of(f - __uint_as_float(hi));
        }
}

// load B fragment (hi+lo) for one k8 from a stride-8 weight array [k][8]
__device__ __forceinline__ void load_bfrag(const float* __restrict__ W, int kg,
                                           int g, int tg, unsigned bhi[2], unsigned blo[2]) {
#pragma unroll
    for (int r = 0; r < 2; ++r) {
        float f = W[(kg + tg + r * 4) * 8 + g];
        unsigned hi = tf32_of(f);
        bhi[r] = hi;
        blo[r] = tf32_of(f - __uint_as_float(hi));
    }
}

__global__ void __launch_bounds__(RTHREADS, 1) gru_recurrent_kernel(
    const float* __restrict__ gk,
    const float* __restrict__ ck,
    float* __restrict__ out)
{
    extern __shared__ float smem[];
    const unsigned sbase = (unsigned)__cvta_generic_to_shared(smem);
    float* Wg0 = smem + OFF_WG0;
    float* Wg1 = smem + OFF_WG1;
    float* Wc  = smem + OFF_WC;
    float* Red = smem + OFF_RED;

    const int tid  = threadIdx.x;
    const int warp = tid >> 5;
    const int lane = tid & 31;
    const int g    = lane >> 2;       // groupID (0..7)
    const int tg   = lane & 3;        // threadID_in_group

    const int p = blockIdx.x;
    const int jbaseA = p * 16;
    const int jbaseB = p * 8;
    const float* __restrict__ Ug = gk + (size_t)DIN * G2;
    const float* __restrict__ Uc = ck + (size_t)DIN * HID;

    // ---- preload weight slices (fp32) ----
    for (int idx = tid; idx < 1024 * 16; idx += RTHREADS) {
        int k = idx >> 4, j = idx & 15;
        float v = Ug[(size_t)k * G2 + jbaseA + j];
        (j < 8 ? Wg0 : Wg1)[k * 8 + (j & 7)] = v;
    }
    for (int idx = tid; idx < 1024 * 8; idx += RTHREADS) {
        int k = idx >> 3, j = idx & 7;
        Wc[k * 8 + j] = Uc[(size_t)k * HID + jbaseB + j];
    }
    __syncthreads();

    unsigned bar_target = 0;

    for (int t = 0; t < TS; ++t) {
        // =================== Phase A: gates ===================
        const int o0 = tid, o1 = tid + 256;
        const int bA0 = o0 >> 4, jA0 = o0 & 15;
        const int bA1 = o1 >> 4, jA1 = o1 & 15;
        float xg0 = __ldcg(&g_XG[((size_t)(bA0 * TS + t)) * G2 + jbaseA + jA0]);
        float xg1 = __ldcg(&g_XG[((size_t)(bA1 * TS + t)) * G2 + jbaseA + jA1]);
        float hE0 = 0.f, hE1 = 0.f;
        if (p < 64) {
            hE0 = __ldcg(&g_h[bA0 * HID + jbaseA + jA0]);
            hE1 = __ldcg(&g_h[bA1 * HID + jbaseA + jA1]);
        }

        issue_chunk(sbase, g_h, 0, 0); CP_COMMIT();

        float cA[4][4];
#pragma unroll
        for (int i = 0; i < 4; ++i)
#pragma unroll
            for (int j = 0; j < 4; ++j) cA[i][j] = 0.0f;

#pragma unroll
        for (int c = 0; c < 4; ++c) {
            if (c < 3) { issue_chunk(sbase, g_h, c + 1, (c + 1) & 1); CP_COMMIT(); CP_WAIT(1); }
            else       { CP_WAIT(0); }
            __syncthreads();
            const float* Hb = smem + OFF_HC + (c & 1) * HCBUF;
#pragma unroll
            for (int ki = 0; ki < 4; ++ki) {
                const int kloc = warp * 32 + ki * 8;
                const int kg = c * CK + kloc;
                unsigned ahi[2][4], alo[2][4];
                load_afrag(Hb, kloc, g, tg, ahi, alo);
                unsigned bhi0[2], blo0[2], bhi1[2], blo1[2];
                load_bfrag(Wg0, kg, g, tg, bhi0, blo0);
                load_bfrag(Wg1, kg, g, tg, bhi1, blo1);
#pragma unroll
                for (int m = 0; m < 2; ++m) {
                    mma_tf32(cA[m * 2 + 0], ahi[m], bhi0);
                    mma_tf32(cA[m * 2 + 0], ahi[m], blo0);
                    mma_tf32(cA[m * 2 + 0], alo[m], bhi0);
                    mma_tf32(cA[m * 2 + 1], ahi[m], bhi1);
                    mma_tf32(cA[m * 2 + 1], ahi[m], blo1);
                    mma_tf32(cA[m * 2 + 1], alo[m], bhi1);
                }
            }
            __syncthreads();
        }
        // write per-warp partials
#pragma unroll
        for (int m = 0; m < 2; ++m)
#pragma unroll
            for (int n = 0; n < 2; ++n) {
                float* dst = &Red[warp * 512 + (m * 16 + g) * 16 + n * 8 + 2 * tg];
                *(float2*)dst         = make_float2(cA[m * 2 + n][0], cA[m * 2 + n][1]);
                *(float2*)(dst + 128) = make_float2(cA[m * 2 + n][2], cA[m * 2 + n][3]);
            }
        __syncthreads();
        {
            float s0 = 0.f, s1 = 0.f;
#pragma unroll
            for (int w = 0; w < 8; ++w) { s0 += Red[w * 512 + o0]; s1 += Red[w * 512 + o1]; }
            float sg0 = 1.0f / (1.0f + expf(-(s0 + xg0)));
            float sg1 = 1.0f / (1.0f + expf(-(s1 + xg1)));
            if (p < 64) {
                __stcg(&g_rh[bA0 * HID + jbaseA + jA0], sg0 * hE0);
                __stcg(&g_rh[bA1 * HID + jbaseA + jA1], sg1 * hE1);
            } else {
                __stcg(&g_u[bA0 * HID + (jbaseA - 1024) + jA0], sg0);
                __stcg(&g_u[bA1 * HID + (jbaseA - 1024) + jA1], sg1);
            }
        }
        grid_barrier_h(&bar_target);

        // =================== Phase B: candidate + update ===================
        const int bB = tid >> 3, jB = tid & 7;
        float xc = __ldcg(&g_XC[((size_t)(bB * TS + t)) * HID + jbaseB + jB]);
        float uv = __ldcg(&g_u[bB * HID + jbaseB + jB]);
        float hv = __ldcg(&g_h[bB * HID + jbaseB + jB]);

        issue_chunk(sbase, g_rh, 0, 0); CP_COMMIT();

        float cB[2][4];
#pragma unroll
        for (int i = 0; i < 2; ++i)
#pragma unroll
            for (int j = 0; j < 4; ++j) cB[i][j] = 0.0f;

#pragma unroll
        for (int c = 0; c < 4; ++c) {
            if (c < 3) { issue_chunk(sbase, g_rh, c + 1, (c + 1) & 1); CP_COMMIT(); CP_WAIT(1); }
            else       { CP_WAIT(0); }
            __syncthreads();
            const float* Hb = smem + OFF_HC + (c & 1) * HCBUF;
#pragma unroll
            for (int ki = 0; ki < 4; ++ki) {
                const int kloc = warp * 32 + ki * 8;
                const int kg = c * CK + kloc;
                unsigned ahi[2][4], alo[2][4];
                load_afrag(Hb, kloc, g, tg, ahi, alo);
                unsigned bhi[2], blo[2];
                load_bfrag(Wc, kg, g, tg, bhi, blo);
#pragma unroll
                for (int m = 0; m < 2; ++m) {
                    mma_tf32(cB[m], ahi[m], bhi);
                    mma_tf32(cB[m], ahi[m], blo);
                    mma_tf32(cB[m], alo[m], bhi);
                }
            }
            __syncthreads();
        }
#pragma unroll
        for (int m = 0; m < 2; ++m) {
            float* dst = &Red[warp * 256 + (m * 16 + g) * 8 + 2 * tg];
            *(float2*)dst        = make_float2(cB[m][0], cB[m][1]);
            *(float2*)(dst + 64) = make_float2(cB[m][2], cB[m][3]);
        }
        __syncthreads();
        {
            float s = 0.f;
#pragma unroll
            for (int w = 0; w < 8; ++w) s += Red[w * 256 + tid];
            float cc = tanhf(s + xc);
            float hn = uv * hv + (1.0f - uv) * cc;
            __stcg(&g_h[bB * HID + jbaseB + jB], hn);
            out[((size_t)bB * TS + t) * HID + jbaseB + jB] = hn;
        }
        grid_barrier_h(&bar_target);
    }
}

// ---------------- launch ----------------
extern "C" void kernel_launch(void* const* d_in, const int* in_sizes, int n_in,
                              void* d_out, int out_size) {
    const float* X  = (const float*)d_in[0];
    const float* gk = (const float*)d_in[1];
    const float* gb = (const float*)d_in[2];
    const float* ck = (const float*)d_in[3];
    const float* cb = (const float*)d_in[4];
    float* out = (float*)d_out;
    (void)in_sizes; (void)n_in; (void)out_size;

    void* pa = nullptr; void* pb = nullptr;
    cudaGetSymbolAddress(&pa, g_XG);
    cudaGetSymbolAddress(&pb, g_XC);
    float* xg_ptr = (float*)pa;
    float* xc_ptr = (float*)pb;

    cudaFuncSetAttribute(gru_recurrent_kernel,
                         cudaFuncAttributeMaxDynamicSharedMemorySize,
                         SMEM_FLOATS * (int)sizeof(float));

    gru_init_kernel<<<RBLOCKS, 256>>>();
    {
        dim3 grid(G2 / BN, (NB * TS) / BM);
        sgemm_bias_kernel<<<grid, 256>>>(X, gk, gb, xg_ptr, NB * TS, G2, DIN, G2);
    }
    {
        dim3 grid(HID / BN, (NB * TS) / BM);
        sgemm_bias_kernel<<<grid, 256>>>(X, ck, cb, xc_ptr, NB * TS, HID, DIN, HID);
    }
    gru_recurrent_kernel<<<RBLOCKS, RTHREADS, SMEM_FLOATS * sizeof(float)>>>(gk, ck, out);
}